// round 1
// baseline (speedup 1.0000x reference)
#include <cuda_runtime.h>
#include <math.h>

#define H 1024
#define L 4096
#define G3 3072
#define NCTA 64     // CTAs per direction in recurrence
#define UNITS 16    // hidden units per CTA (16 warps, 1 unit/warp)

// Scratch: precomputed input projections gi = Wih @ x_t + bih, per direction.
__device__ float g_Gi[2][L][G3];            // ~100.7 MB
__device__ unsigned int g_ctr[2 * L];       // per-step arrival counters

// ---------------------------------------------------------------------------
// Reset counters (runs first on every launch/replay -> deterministic)
// ---------------------------------------------------------------------------
__global__ void reset_kernel() {
    int i = blockIdx.x * blockDim.x + threadIdx.x;
    for (int k = i; k < 2 * L; k += gridDim.x * blockDim.x) g_ctr[k] = 0u;
}

// ---------------------------------------------------------------------------
// Phase 1: Gi[d][t][n] = sum_k x[t][k] * W[n][k] + b[n]
// SGEMM-NT: A = x [4096 x 1024], B = W [3072 x 1024], C = Gi[d] [4096 x 3072]
// Tile: BM=128, BN=64, BK=16, 256 threads, 8x4 microtile.
// ---------------------------------------------------------------------------
__global__ __launch_bounds__(256) void gi_gemm(
    const float* __restrict__ x,
    const float* __restrict__ Wf, const float* __restrict__ bf,
    const float* __restrict__ Wr, const float* __restrict__ br)
{
    const int d  = blockIdx.z;
    const float* __restrict__ W = d ? Wr : Wf;
    const float* __restrict__ b = d ? br : bf;
    const int m0 = blockIdx.y * 128;
    const int n0 = blockIdx.x * 64;

    __shared__ float As[16][132];  // [k][m], padded
    __shared__ float Bs[16][68];   // [k][n], padded

    const int tid = threadIdx.x;
    const int tx  = tid & 15;      // n dir: 16 groups * 4 cols
    const int ty  = tid >> 4;      // m dir: 16 groups * 8 rows

    float acc[8][4];
    #pragma unroll
    for (int i = 0; i < 8; ++i)
        #pragma unroll
        for (int j = 0; j < 4; ++j) acc[i][j] = 0.0f;

    for (int k0 = 0; k0 < H; k0 += 16) {
        // Load A tile: 128 rows x 16 k  = 512 float4
        #pragma unroll
        for (int it = 0; it < 2; ++it) {
            int idx = tid + it * 256;
            int row = idx >> 2, kq = idx & 3;
            float4 v = *(const float4*)(x + (size_t)(m0 + row) * H + k0 + kq * 4);
            As[kq * 4 + 0][row] = v.x;
            As[kq * 4 + 1][row] = v.y;
            As[kq * 4 + 2][row] = v.z;
            As[kq * 4 + 3][row] = v.w;
        }
        // Load B tile: 64 rows x 16 k = 256 float4
        {
            int row = tid >> 2, kq = tid & 3;
            float4 v = *(const float4*)(W + (size_t)(n0 + row) * H + k0 + kq * 4);
            Bs[kq * 4 + 0][row] = v.x;
            Bs[kq * 4 + 1][row] = v.y;
            Bs[kq * 4 + 2][row] = v.z;
            Bs[kq * 4 + 3][row] = v.w;
        }
        __syncthreads();

        #pragma unroll
        for (int kk = 0; kk < 16; ++kk) {
            float4 a0 = *(const float4*)&As[kk][ty * 8];
            float4 a1 = *(const float4*)&As[kk][ty * 8 + 4];
            float4 bb = *(const float4*)&Bs[kk][tx * 4];
            float a[8] = {a0.x, a0.y, a0.z, a0.w, a1.x, a1.y, a1.z, a1.w};
            float bv[4] = {bb.x, bb.y, bb.z, bb.w};
            #pragma unroll
            for (int i = 0; i < 8; ++i)
                #pragma unroll
                for (int j = 0; j < 4; ++j)
                    acc[i][j] = fmaf(a[i], bv[j], acc[i][j]);
        }
        __syncthreads();
    }

    // Epilogue: add bias, store to g_Gi[d]
    float* __restrict__ C = &g_Gi[d][0][0];
    float4 bias = *(const float4*)(b + n0 + tx * 4);
    #pragma unroll
    for (int i = 0; i < 8; ++i) {
        int m = m0 + ty * 8 + i;
        float4 o;
        o.x = acc[i][0] + bias.x;
        o.y = acc[i][1] + bias.y;
        o.z = acc[i][2] + bias.z;
        o.w = acc[i][3] + bias.w;
        *(float4*)(C + (size_t)m * G3 + n0 + tx * 4) = o;
    }
}

// ---------------------------------------------------------------------------
// Phase 2: persistent register-resident GRU recurrence.
// 128 CTAs total (64 per direction), 512 threads each.
// Warp w of CTA handles hidden unit u = cta*16 + w, holding the 3 Whh rows
// (r, z, n gates) for that unit entirely in registers (96 regs/lane).
// Cross-CTA per-step sync via release/acquire flag barrier in L2.
// ---------------------------------------------------------------------------
__device__ __forceinline__ float sigm(float v) {
    return 1.0f / (1.0f + __expf(-v));
}
__device__ __forceinline__ float tanh_fast(float v) {
    // tanh(x) = 2/(1+exp(-2x)) - 1 ; saturates correctly at +-inf
    return 2.0f / (1.0f + __expf(-2.0f * v)) - 1.0f;
}

__global__ __launch_bounds__(512, 1) void gru_recur(
    const float* __restrict__ Whh_f, const float* __restrict__ bhh_f,
    const float* __restrict__ Whh_r, const float* __restrict__ bhh_r,
    float* __restrict__ out)
{
    const int bx  = blockIdx.x;
    const int d   = (bx >= NCTA) ? 1 : 0;
    const int cta = d ? bx - NCTA : bx;
    const int u0  = cta * UNITS;
    const int tid = threadIdx.x;
    const int w   = tid >> 5;
    const int l   = tid & 31;
    const int u   = u0 + w;

    const float* __restrict__ Whh = d ? Whh_r : Whh_f;
    const float* __restrict__ bhh = d ? bhh_r : bhh_f;
    const float* __restrict__ Gi  = &g_Gi[d][0][0];
    unsigned int* ctr = g_ctr + d * L;

    __shared__ float h_s[H];

    // Load this warp's 3 weight rows into registers.
    // Lane l holds W[row][128*c + 4*l .. +3] for c = 0..7 (matches SMEM h reads).
    float4 w0[8], w1[8], w2[8];
    {
        const float* r0 = Whh + (size_t)(u         ) * H + 4 * l;
        const float* r1 = Whh + (size_t)(u + H     ) * H + 4 * l;
        const float* r2 = Whh + (size_t)(u + 2 * H ) * H + 4 * l;
        #pragma unroll
        for (int c = 0; c < 8; ++c) {
            w0[c] = *(const float4*)(r0 + c * 128);
            w1[c] = *(const float4*)(r1 + c * 128);
            w2[c] = *(const float4*)(r2 + c * 128);
        }
    }
    const float b_r = bhh[u];
    const float b_z = bhh[u + H];
    const float b_n = bhh[u + 2 * H];

    for (int s = 0; s < L; ++s) {
        const int t = d ? (L - 1 - s) : s;

        // Stage h_prev into shared memory.
        if (s == 0) {
            if (tid < 256) ((float4*)h_s)[tid] = make_float4(0.f, 0.f, 0.f, 0.f);
        } else {
            const int tprev = d ? (t + 1) : (t - 1);
            const float* hrow = out + (size_t)tprev * (2 * H) + d * H;
            if (tid < 256) ((float4*)h_s)[tid] = ((const float4*)hrow)[tid];
        }
        __syncthreads();

        // Prefetch input-projection gates (lane 0 only needs them).
        float gi_r = 0.f, gi_z = 0.f, gi_n = 0.f;
        if (l == 0) {
            const float* g = Gi + (size_t)t * G3;
            gi_r = g[u];
            gi_z = g[u + H];
            gi_n = g[u + 2 * H];
        }

        // Dot products: 3 rows x 1024 over 32 lanes.
        float a0 = 0.f, a1 = 0.f, a2 = 0.f;
        #pragma unroll
        for (int c = 0; c < 8; ++c) {
            float4 h4 = ((const float4*)h_s)[c * 32 + l];
            a0 = fmaf(w0[c].x, h4.x, a0); a0 = fmaf(w0[c].y, h4.y, a0);
            a0 = fmaf(w0[c].z, h4.z, a0); a0 = fmaf(w0[c].w, h4.w, a0);
            a1 = fmaf(w1[c].x, h4.x, a1); a1 = fmaf(w1[c].y, h4.y, a1);
            a1 = fmaf(w1[c].z, h4.z, a1); a1 = fmaf(w1[c].w, h4.w, a1);
            a2 = fmaf(w2[c].x, h4.x, a2); a2 = fmaf(w2[c].y, h4.y, a2);
            a2 = fmaf(w2[c].z, h4.z, a2); a2 = fmaf(w2[c].w, h4.w, a2);
        }
        #pragma unroll
        for (int o = 16; o > 0; o >>= 1) {
            a0 += __shfl_xor_sync(0xffffffffu, a0, o);
            a1 += __shfl_xor_sync(0xffffffffu, a1, o);
            a2 += __shfl_xor_sync(0xffffffffu, a2, o);
        }

        if (l == 0) {
            float r  = sigm(gi_r + a0 + b_r);
            float z  = sigm(gi_z + a1 + b_z);
            float n  = tanh_fast(gi_n + r * (a2 + b_n));
            float hp = h_s[u];
            float hn = fmaf(z, hp - n, n);   // (1-z)*n + z*hp
            out[(size_t)t * (2 * H) + d * H + u] = hn;
            if (s == L - 1) {
                // hidden and projected_output (identical), appended after outputs
                const size_t hid_off  = (size_t)L * (2 * H);
                out[hid_off + d * H + u]             = hn;
                out[hid_off + 2 * H + d * H + u]     = hn;
            }
        }

        // Release our writes, arrive, spin until all CTAs of this direction done.
        __threadfence();
        __syncthreads();
        if (tid == 0) {
            atomicAdd(&ctr[s], 1u);
            while (atomicAdd(&ctr[s], 0u) < (unsigned)NCTA) { }
            __threadfence();
        }
        __syncthreads();
    }
}

// ---------------------------------------------------------------------------
// Launch
// ---------------------------------------------------------------------------
extern "C" void kernel_launch(void* const* d_in, const int* in_sizes, int n_in,
                              void* d_out, int out_size)
{
    const float* x    = (const float*)d_in[0];
    const float* fWih = (const float*)d_in[1];
    const float* fWhh = (const float*)d_in[2];
    const float* fbih = (const float*)d_in[3];
    const float* fbhh = (const float*)d_in[4];
    const float* rWih = (const float*)d_in[5];
    const float* rWhh = (const float*)d_in[6];
    const float* rbih = (const float*)d_in[7];
    const float* rbhh = (const float*)d_in[8];
    float* out = (float*)d_out;

    reset_kernel<<<8, 256>>>();

    dim3 ggrid(G3 / 64, L / 128, 2);
    gi_gemm<<<ggrid, 256>>>(x, fWih, fbih, rWih, rbih);

    gru_recur<<<2 * NCTA, 512>>>(fWhh, fbhh, rWhh, rbhh, out);
}

// round 2
// speedup vs baseline: 1.4465x; 1.4465x over previous
#include <cuda_runtime.h>
#include <math.h>

#define H 1024
#define L 4096
#define G3 3072
#define NCTA 64     // CTAs per direction in recurrence
#define UNITS 16    // hidden units per CTA (16 warps, 1 unit/warp)

typedef unsigned long long u64;

// Scratch: precomputed input projections gi = Wih @ x_t + bih, per direction.
__device__ float g_Gi[2][L][G3];            // ~100.7 MB
__device__ unsigned int g_ctr[2 * L];       // per-step arrival counters
__device__ float g_h[2][2][H];              // [dir][step parity][H] h exchange buffer

// ---------------------------------------------------------------------------
// packed f32x2 FMA (FFMA2) — only reachable via PTX
// ---------------------------------------------------------------------------
__device__ __forceinline__ void ffma2(u64& acc, u64 a, u64 b) {
    asm("fma.rn.f32x2 %0, %1, %2, %3;" : "=l"(acc) : "l"(a), "l"(b), "l"(acc));
}
__device__ __forceinline__ float hsum2(u64 v) {
    float lo, hi;
    asm("mov.b64 {%0, %1}, %2;" : "=f"(lo), "=f"(hi) : "l"(v));
    return lo + hi;
}
__device__ __forceinline__ void arrive_release(unsigned int* p) {
    asm volatile("red.release.gpu.global.add.u32 [%0], 1;" :: "l"(p) : "memory");
}
__device__ __forceinline__ unsigned int ld_acquire(const unsigned int* p) {
    unsigned int v;
    asm volatile("ld.acquire.gpu.global.u32 %0, [%1];" : "=r"(v) : "l"(p) : "memory");
    return v;
}

// ---------------------------------------------------------------------------
// Reset counters (runs first on every launch/replay -> deterministic)
// ---------------------------------------------------------------------------
__global__ void reset_kernel() {
    int i = blockIdx.x * blockDim.x + threadIdx.x;
    for (int k = i; k < 2 * L; k += gridDim.x * blockDim.x) g_ctr[k] = 0u;
}

// ---------------------------------------------------------------------------
// Phase 1: Gi[d][t][n] = sum_k x[t][k] * W[n][k] + b[n]   (unchanged from R1)
// ---------------------------------------------------------------------------
__global__ __launch_bounds__(256) void gi_gemm(
    const float* __restrict__ x,
    const float* __restrict__ Wf, const float* __restrict__ bf,
    const float* __restrict__ Wr, const float* __restrict__ br)
{
    const int d  = blockIdx.z;
    const float* __restrict__ W = d ? Wr : Wf;
    const float* __restrict__ b = d ? br : bf;
    const int m0 = blockIdx.y * 128;
    const int n0 = blockIdx.x * 64;

    __shared__ float As[16][132];
    __shared__ float Bs[16][68];

    const int tid = threadIdx.x;
    const int tx  = tid & 15;
    const int ty  = tid >> 4;

    float acc[8][4];
    #pragma unroll
    for (int i = 0; i < 8; ++i)
        #pragma unroll
        for (int j = 0; j < 4; ++j) acc[i][j] = 0.0f;

    for (int k0 = 0; k0 < H; k0 += 16) {
        #pragma unroll
        for (int it = 0; it < 2; ++it) {
            int idx = tid + it * 256;
            int row = idx >> 2, kq = idx & 3;
            float4 v = *(const float4*)(x + (size_t)(m0 + row) * H + k0 + kq * 4);
            As[kq * 4 + 0][row] = v.x;
            As[kq * 4 + 1][row] = v.y;
            As[kq * 4 + 2][row] = v.z;
            As[kq * 4 + 3][row] = v.w;
        }
        {
            int row = tid >> 2, kq = tid & 3;
            float4 v = *(const float4*)(W + (size_t)(n0 + row) * H + k0 + kq * 4);
            Bs[kq * 4 + 0][row] = v.x;
            Bs[kq * 4 + 1][row] = v.y;
            Bs[kq * 4 + 2][row] = v.z;
            Bs[kq * 4 + 3][row] = v.w;
        }
        __syncthreads();

        #pragma unroll
        for (int kk = 0; kk < 16; ++kk) {
            float4 a0 = *(const float4*)&As[kk][ty * 8];
            float4 a1 = *(const float4*)&As[kk][ty * 8 + 4];
            float4 bb = *(const float4*)&Bs[kk][tx * 4];
            float a[8] = {a0.x, a0.y, a0.z, a0.w, a1.x, a1.y, a1.z, a1.w};
            float bv[4] = {bb.x, bb.y, bb.z, bb.w};
            #pragma unroll
            for (int i = 0; i < 8; ++i)
                #pragma unroll
                for (int j = 0; j < 4; ++j)
                    acc[i][j] = fmaf(a[i], bv[j], acc[i][j]);
        }
        __syncthreads();
    }

    float* __restrict__ C = &g_Gi[d][0][0];
    float4 bias = *(const float4*)(b + n0 + tx * 4);
    #pragma unroll
    for (int i = 0; i < 8; ++i) {
        int m = m0 + ty * 8 + i;
        float4 o;
        o.x = acc[i][0] + bias.x;
        o.y = acc[i][1] + bias.y;
        o.z = acc[i][2] + bias.z;
        o.w = acc[i][3] + bias.w;
        *(float4*)(C + (size_t)m * G3 + n0 + tx * 4) = o;
    }
}

// ---------------------------------------------------------------------------
// Phase 2: persistent register-resident GRU recurrence, FFMA2 + rel/acq sync.
// ---------------------------------------------------------------------------
__device__ __forceinline__ float sigm(float v) {
    return 1.0f / (1.0f + __expf(-v));
}
__device__ __forceinline__ float tanh_fast(float v) {
    return 2.0f / (1.0f + __expf(-2.0f * v)) - 1.0f;
}

__global__ __launch_bounds__(512, 1) void gru_recur(
    const float* __restrict__ Whh_f, const float* __restrict__ bhh_f,
    const float* __restrict__ Whh_r, const float* __restrict__ bhh_r,
    float* __restrict__ out)
{
    const int bx  = blockIdx.x;
    const int d   = (bx >= NCTA) ? 1 : 0;
    const int cta = d ? bx - NCTA : bx;
    const int u0  = cta * UNITS;
    const int tid = threadIdx.x;
    const int w   = tid >> 5;
    const int l   = tid & 31;
    const int u   = u0 + w;

    const float* __restrict__ Whh = d ? Whh_r : Whh_f;
    const float* __restrict__ bhh = d ? bhh_r : bhh_f;
    const float* __restrict__ Gi  = &g_Gi[d][0][0];
    unsigned int* ctr = g_ctr + d * L;
    float* hbuf0 = &g_h[d][0][0];
    float* hbuf1 = &g_h[d][1][0];

    __shared__ float h_s[H];
    const u64* hs64 = (const u64*)h_s;

    // Load this warp's 3 weight rows into registers as packed f32x2 pairs.
    // Lane l holds floats [128*c + 4*l .. +3] of each row, c = 0..7.
    u64 w0[16], w1[16], w2[16];
    {
        const u64* r0 = (const u64*)(Whh + (size_t)(u         ) * H + 4 * l);
        const u64* r1 = (const u64*)(Whh + (size_t)(u + H     ) * H + 4 * l);
        const u64* r2 = (const u64*)(Whh + (size_t)(u + 2 * H ) * H + 4 * l);
        #pragma unroll
        for (int c = 0; c < 8; ++c) {
            w0[2*c] = r0[c*64]; w0[2*c+1] = r0[c*64+1];
            w1[2*c] = r1[c*64]; w1[2*c+1] = r1[c*64+1];
            w2[2*c] = r2[c*64]; w2[2*c+1] = r2[c*64+1];
        }
    }
    const float b_r = bhh[u];
    const float b_z = bhh[u + H];
    const float b_n = bhh[u + 2 * H];

    for (int s = 0; s < L; ++s) {
        const int t = d ? (L - 1 - s) : s;

        // Prefetch input-projection gates (independent of the h dependency).
        float gi_r = 0.f, gi_z = 0.f, gi_n = 0.f;
        if (l == 0) {
            const float* g = Gi + (size_t)t * G3;
            gi_r = __ldg(g + u);
            gi_z = __ldg(g + u + H);
            gi_n = __ldg(g + u + 2 * H);
        }

        // Wait for previous step's h, stage into SMEM (L2-only loads).
        if (s == 0) {
            if (tid < 256) ((float4*)h_s)[tid] = make_float4(0.f, 0.f, 0.f, 0.f);
        } else {
            if (tid == 0) {
                while (ld_acquire(&ctr[s - 1]) < (unsigned)NCTA) { }
            }
            __syncthreads();
            const float4* src = (const float4*)(((s - 1) & 1) ? hbuf1 : hbuf0);
            if (tid < 256) ((float4*)h_s)[tid] = __ldcg(src + tid);
        }
        __syncthreads();

        // Dot products: 3 rows x 1024, packed f32x2 (48 FFMA2 per lane).
        u64 a0 = 0ull, a1 = 0ull, a2 = 0ull;
        #pragma unroll
        for (int c = 0; c < 8; ++c) {
            u64 h0 = hs64[c * 64 + 2 * l];
            u64 h1 = hs64[c * 64 + 2 * l + 1];
            ffma2(a0, w0[2*c], h0); ffma2(a0, w0[2*c+1], h1);
            ffma2(a1, w1[2*c], h0); ffma2(a1, w1[2*c+1], h1);
            ffma2(a2, w2[2*c], h0); ffma2(a2, w2[2*c+1], h1);
        }
        float s0 = hsum2(a0), s1 = hsum2(a1), s2 = hsum2(a2);
        #pragma unroll
        for (int o = 16; o > 0; o >>= 1) {
            s0 += __shfl_xor_sync(0xffffffffu, s0, o);
            s1 += __shfl_xor_sync(0xffffffffu, s1, o);
            s2 += __shfl_xor_sync(0xffffffffu, s2, o);
        }

        if (l == 0) {
            float r  = sigm(gi_r + s0 + b_r);
            float z  = sigm(gi_z + s1 + b_z);
            float n  = tanh_fast(gi_n + r * (s2 + b_n));
            float hp = h_s[u];
            float hn = fmaf(z, hp - n, n);   // (1-z)*n + z*hp
            __stcg(((s & 1) ? hbuf1 : hbuf0) + u, hn);
            out[(size_t)t * (2 * H) + d * H + u] = hn;
            if (s == L - 1) {
                const size_t hid_off = (size_t)L * (2 * H);
                out[hid_off + d * H + u]         = hn;
                out[hid_off + 2 * H + d * H + u] = hn;
            }
        }

        // All warps' h stores done -> cumulative release arrive.
        __syncthreads();
        if (tid == 0) arrive_release(&ctr[s]);
    }
}

// ---------------------------------------------------------------------------
// Launch
// ---------------------------------------------------------------------------
extern "C" void kernel_launch(void* const* d_in, const int* in_sizes, int n_in,
                              void* d_out, int out_size)
{
    const float* x    = (const float*)d_in[0];
    const float* fWih = (const float*)d_in[1];
    const float* fWhh = (const float*)d_in[2];
    const float* fbih = (const float*)d_in[3];
    const float* fbhh = (const float*)d_in[4];
    const float* rWih = (const float*)d_in[5];
    const float* rWhh = (const float*)d_in[6];
    const float* rbih = (const float*)d_in[7];
    const float* rbhh = (const float*)d_in[8];
    float* out = (float*)d_out;

    reset_kernel<<<8, 256>>>();

    dim3 ggrid(G3 / 64, L / 128, 2);
    gi_gemm<<<ggrid, 256>>>(x, fWih, fbih, rWih, rbih);

    gru_recur<<<2 * NCTA, 512>>>(fWhh, fbhh, rWhh, rbhh, out);
}